// round 13
// baseline (speedup 1.0000x reference)
#include <cuda_runtime.h>
#include <cstdint>

#define NTOT 8192
#define NHID 256

// ---------------- scratch (allocation-free rule: __device__ globals) --------
__device__ float g_sT[NHID * NTOT];          // support^T, tf32-rounded  [256, 8192]
__device__ float g_h[NTOT * NHID];           // h, tf32-rounded          [8192, 256]
__device__ float g_part[2ll * NTOT * NHID];  // split-K partials of GEMM-2

// ---------------- portable helpers (plain sm_103 target) --------------------
__device__ __forceinline__ float tf32r(float x) {
    uint32_t r;
    asm("cvt.rna.tf32.f32 %0, %1;" : "=r"(r) : "f"(x));
    return __uint_as_float(r);
}
__device__ __forceinline__ uint32_t smem_u32(const void* p) {
    uint32_t a;
    asm("{ .reg .u64 t; cvta.to.shared.u64 t, %1; cvt.u32.u64 %0, t; }"
        : "=r"(a) : "l"(p));
    return a;
}
__device__ __forceinline__ void cp16(uint32_t dst, const void* src) {
    asm volatile("cp.async.cg.shared.global [%0], [%1], 16;"
                 :: "r"(dst), "l"(__cvta_generic_to_global(src)));
}
#define CP_COMMIT() asm volatile("cp.async.commit_group;")
#define CP_WAIT0()  asm volatile("cp.async.wait_group 0;")
#define CP_WAIT1()  asm volatile("cp.async.wait_group 1;")

// mma.sync m16n8k8 tf32 -> f32 (sm_80+ portable)
__device__ __forceinline__ void mma_tf32(float* c, const uint32_t* a, const uint32_t* b) {
    asm volatile(
        "mma.sync.aligned.m16n8k8.row.col.f32.tf32.tf32.f32 "
        "{%0,%1,%2,%3}, {%4,%5,%6,%7}, {%8,%9}, {%0,%1,%2,%3};"
        : "+f"(c[0]), "+f"(c[1]), "+f"(c[2]), "+f"(c[3])
        : "r"(a[0]), "r"(a[1]), "r"(a[2]), "r"(a[3]), "r"(b[0]), "r"(b[1]));
}

// ---------------- smem: 2 stages x (A,B) tiles of 128x16 f32, stride 20 -----
#define TS 20                     // row stride in floats (16 data + 4 pad)
#define TILE_F (128 * TS)         // 2560 floats
#define STAGE_F (2 * TILE_F)      // A + B
// total static: 2 * STAGE_F * 4 = 40960 B  (< 48KB, no opt-in needed)

// ---------------- GEMM-1: fp32 SIMT, epilogue -> support^T (tf32-rounded) ---
__global__ __launch_bounds__(256, 2)
void gemm1_kernel(const float* __restrict__ A, const float* __restrict__ B,
                  const float* __restrict__ bias) {
    __shared__ float As[8][128];
    __shared__ float Bs[8][128];
    const int tid = threadIdx.x;
    const int tx = tid & 15, ty = tid >> 4;
    const int m0 = blockIdx.y * 128, n0 = blockIdx.x * 128;
    float acc[8][8];
#pragma unroll
    for (int i = 0; i < 8; i++)
#pragma unroll
        for (int j = 0; j < 8; j++) acc[i][j] = 0.0f;

    const int a_row = tid >> 1, a_k4 = (tid & 1) * 4;
    const int bn_k = tid >> 5, bn_n4 = (tid & 31) * 4;

    for (int k0 = 0; k0 < NHID; k0 += 8) {
        float4 v = *reinterpret_cast<const float4*>(&A[(long long)(m0 + a_row) * NHID + k0 + a_k4]);
        As[a_k4 + 0][a_row] = v.x; As[a_k4 + 1][a_row] = v.y;
        As[a_k4 + 2][a_row] = v.z; As[a_k4 + 3][a_row] = v.w;
        float4 w = *reinterpret_cast<const float4*>(&B[(long long)(k0 + bn_k) * NHID + n0 + bn_n4]);
        *reinterpret_cast<float4*>(&Bs[bn_k][bn_n4]) = w;
        __syncthreads();
#pragma unroll
        for (int kk = 0; kk < 8; kk++) {
            float a[8], b[8];
            float4 a0 = *reinterpret_cast<const float4*>(&As[kk][ty * 4]);
            float4 a1 = *reinterpret_cast<const float4*>(&As[kk][64 + ty * 4]);
            float4 b0 = *reinterpret_cast<const float4*>(&Bs[kk][tx * 4]);
            float4 b1 = *reinterpret_cast<const float4*>(&Bs[kk][64 + tx * 4]);
            a[0]=a0.x;a[1]=a0.y;a[2]=a0.z;a[3]=a0.w;a[4]=a1.x;a[5]=a1.y;a[6]=a1.z;a[7]=a1.w;
            b[0]=b0.x;b[1]=b0.y;b[2]=b0.z;b[3]=b0.w;b[4]=b1.x;b[5]=b1.y;b[6]=b1.z;b[7]=b1.w;
#pragma unroll
            for (int i = 0; i < 8; i++)
#pragma unroll
                for (int j = 0; j < 8; j++) acc[i][j] = fmaf(a[i], b[j], acc[i][j]);
        }
        __syncthreads();
    }
#pragma unroll
    for (int i = 0; i < 8; i++) {
        const int row = m0 + ((i < 4) ? (ty * 4 + i) : (64 + ty * 4 + (i - 4)));
#pragma unroll
        for (int j = 0; j < 8; j++) {
            const int col = n0 + ((j < 4) ? (tx * 4 + j) : (64 + tx * 4 + (j - 4)));
            g_sT[(size_t)col * NTOT + row] = tf32r(acc[i][j] + bias[col]);
        }
    }
}

// ---------------- mma.sync tf32 kernels --------------------------------------
// MODE 0: GEMM-2 partials. grid (4, 64): nx=x&1, kz=x>>1.  writes g_part.
// MODE 1: GEMM-3 h h^T, symmetric. grid (64, 64); CTAs with x<y exit;
//         block (y,x) computed once, written at (y,x) and (x,y)^T.
template <int MODE>
__global__ __launch_bounds__(256, 2)
void mma_tf32_kernel(const float* __restrict__ A32, float* __restrict__ C) {
    __shared__ float sm[2 * STAGE_F];   // 40960 B static
    const uint32_t sb = smem_u32(sm);

    if (MODE == 1 && blockIdx.x < blockIdx.y) return;  // symmetry: upper triangle only

    const int tid = threadIdx.x;
    const int w = tid >> 5, lane = tid & 31;
    const int g = lane >> 2, t4 = lane & 3;
    const int wm = (w & 3) * 32, wn = (w >> 2) * 64;

    const int m0 = blockIdx.y * 128;
    const int nx = (MODE == 0) ? (blockIdx.x & 1) : blockIdx.x;
    const int kz = (MODE == 0) ? (blockIdx.x >> 1) : 0;
    const int n0 = nx * 128;
    const int kb = (MODE == 0) ? kz * (NTOT / 2) : 0;
    const int T  = (MODE == 0) ? (NTOT / 2) / 16 : NHID / 16;

    float acc[2][8][4];
#pragma unroll
    for (int mi = 0; mi < 2; mi++)
#pragma unroll
        for (int ni = 0; ni < 8; ni++)
#pragma unroll
            for (int q = 0; q < 4; q++) acc[mi][ni][q] = 0.0f;

    float4 areg0, areg1;                 // MODE 0: adj staging (LDG early, STS late)
    const int a_row = tid >> 1, a_c = (tid & 1) * 8;

    // ---- stage loaders ----
    auto cpB = [&](int k0, int s) {
        const uint32_t base = sb + (uint32_t)(s * STAGE_F + TILE_F) * 4u;
        const float* src = (MODE == 0) ? g_sT : g_h;
        const long long ld = (MODE == 0) ? NTOT : NHID;
#pragma unroll
        for (int i = 0; i < 2; i++) {
            int j = i * 256 + tid;
            int row = j >> 2, ch = j & 3;
            cp16(base + row * (TS * 4) + ch * 16,
                 src + (long long)(n0 + row) * ld + k0 + ch * 4);
        }
    };
    auto cpA = [&](int k0, int s) {
        const uint32_t base = sb + (uint32_t)(s * STAGE_F) * 4u;
#pragma unroll
        for (int i = 0; i < 2; i++) {
            int j = i * 256 + tid;
            int row = j >> 2, ch = j & 3;
            cp16(base + row * (TS * 4) + ch * 16,
                 g_h + (long long)(m0 + row) * NHID + k0 + ch * 4);
        }
    };
    auto ldgA = [&](int k0) {
        const float* p = A32 + (long long)(m0 + a_row) * NTOT + k0 + a_c;
        areg0 = *reinterpret_cast<const float4*>(p);
        areg1 = *reinterpret_cast<const float4*>(p + 4);
    };
    auto stsA = [&](int s) {
        float* dst = sm + s * STAGE_F + a_row * TS + a_c;
        dst[0] = tf32r(areg0.x); dst[1] = tf32r(areg0.y);
        dst[2] = tf32r(areg0.z); dst[3] = tf32r(areg0.w);
        dst[4] = tf32r(areg1.x); dst[5] = tf32r(areg1.y);
        dst[6] = tf32r(areg1.z); dst[7] = tf32r(areg1.w);
    };

    // ---- prologue: stage 0 ----
    if (MODE == 0) { ldgA(kb); stsA(0); cpB(kb, 0); }
    else           { cpA(0, 0); cpB(0, 0); }
    CP_COMMIT();

    int buf = 0;
    for (int t = 0; t < T; t++) {
        if (t + 1 < T) {
            const int k0 = kb + (t + 1) * 16;
            if (MODE == 0) { ldgA(k0); cpB(k0, buf ^ 1); }
            else           { cpA(k0, buf ^ 1); cpB(k0, buf ^ 1); }
            CP_COMMIT();
            CP_WAIT1();
        } else {
            CP_WAIT0();
        }
        __syncthreads();

        const uint32_t* At = reinterpret_cast<const uint32_t*>(sm + buf * STAGE_F);
        const uint32_t* Bt = reinterpret_cast<const uint32_t*>(sm + buf * STAGE_F + TILE_F);
#pragma unroll
        for (int ks = 0; ks < 2; ks++) {
            const int k0 = ks * 8;
            uint32_t Af[2][4];
#pragma unroll
            for (int mi = 0; mi < 2; mi++) {
                const int r = wm + mi * 16 + g;
                Af[mi][0] = At[r * TS + k0 + t4];
                Af[mi][1] = At[(r + 8) * TS + k0 + t4];
                Af[mi][2] = At[r * TS + k0 + t4 + 4];
                Af[mi][3] = At[(r + 8) * TS + k0 + t4 + 4];
            }
            uint32_t Bf[8][2];
#pragma unroll
            for (int ni = 0; ni < 8; ni++) {
                const int rn = wn + ni * 8 + g;
                Bf[ni][0] = Bt[rn * TS + k0 + t4];
                Bf[ni][1] = Bt[rn * TS + k0 + t4 + 4];
            }
#pragma unroll
            for (int mi = 0; mi < 2; mi++)
#pragma unroll
                for (int ni = 0; ni < 8; ni++)
                    mma_tf32(acc[mi][ni], Af[mi], Bf[ni]);
        }

        if (MODE == 0 && t + 1 < T) stsA(buf ^ 1);
        __syncthreads();
        buf ^= 1;
    }

    // ---- epilogue ----
    if (MODE == 0) {
        float* dst = g_part + (size_t)kz * NTOT * NHID;
#pragma unroll
        for (int mi = 0; mi < 2; mi++)
#pragma unroll
            for (int ni = 0; ni < 8; ni++) {
                const int row = m0 + wm + mi * 16 + g;
                const int col = n0 + wn + ni * 8 + t4 * 2;
                *reinterpret_cast<float2*>(&dst[(size_t)row * NHID + col]) =
                    make_float2(acc[mi][ni][0], acc[mi][ni][1]);
                *reinterpret_cast<float2*>(&dst[(size_t)(row + 8) * NHID + col]) =
                    make_float2(acc[mi][ni][2], acc[mi][ni][3]);
            }
    } else {
        // symmetric dual-write: stage 64-row halves at stride 133
        // (odd stride -> conflict-free scalar reads in BOTH directions)
        const bool offdiag = (m0 != n0);
#pragma unroll
        for (int half = 0; half < 2; half++) {
            if (((w & 3) >> 1) == half) {
#pragma unroll
                for (int mi = 0; mi < 2; mi++)
#pragma unroll
                    for (int ni = 0; ni < 8; ni++) {
                        const int lrow = wm - half * 64 + mi * 16 + g;
                        const int col = wn + ni * 8 + t4 * 2;
                        sm[lrow * 133 + col]           = acc[mi][ni][0];
                        sm[lrow * 133 + col + 1]       = acc[mi][ni][1];
                        sm[(lrow + 8) * 133 + col]     = acc[mi][ni][2];
                        sm[(lrow + 8) * 133 + col + 1] = acc[mi][ni][3];
                    }
            }
            __syncthreads();
            // normal write: C[m0+64h+row][n0+c]
#pragma unroll
            for (int i = 0; i < 32; i++) {
                const int q = i * 256 + tid;
                const int row = q >> 7, c = q & 127;
                C[(size_t)(m0 + half * 64 + row) * NTOT + n0 + c] = sm[row * 133 + c];
            }
            // transposed write: C[n0+c][m0+64h+r]
            if (offdiag) {
                const int r = tid & 63, cb = tid >> 6;
#pragma unroll
                for (int c = 0; c < 128; c += 4) {
                    C[(size_t)(n0 + c + cb) * NTOT + m0 + half * 64 + r] =
                        sm[r * 133 + c + cb];
                }
            }
            __syncthreads();
        }
    }
}

// ---------------- combine: h = tf32(relu(p0 + p1)) ---------------------------
__global__ __launch_bounds__(256, 4)
void combine_kernel() {
    const int i4 = (blockIdx.x * 256 + threadIdx.x) * 4;
    float4 a = *reinterpret_cast<const float4*>(&g_part[i4]);
    float4 b = *reinterpret_cast<const float4*>(&g_part[(size_t)NTOT * NHID + i4]);
    float4 o;
    o.x = tf32r(fmaxf(a.x + b.x, 0.0f));
    o.y = tf32r(fmaxf(a.y + b.y, 0.0f));
    o.z = tf32r(fmaxf(a.z + b.z, 0.0f));
    o.w = tf32r(fmaxf(a.w + b.w, 0.0f));
    *reinterpret_cast<float4*>(&g_h[i4]) = o;
}

// ---------------- launch -----------------------------------------------------
extern "C" void kernel_launch(void* const* d_in, const int* in_sizes, int n_in,
                              void* d_out, int out_size) {
    const float* x   = (const float*)d_in[0];
    const float* adj = (const float*)d_in[1];
    const float* W   = (const float*)d_in[2];
    const float* b   = (const float*)d_in[3];
    float* out = (float*)d_out;

    // 1) support^T = tf32(x @ W + b)^T
    gemm1_kernel<<<dim3(NHID / 128, NTOT / 128), 256>>>(x, W, b);
    // 2) split-K partials of adj @ support  (mma.sync tf32)
    mma_tf32_kernel<0><<<dim3(4, NTOT / 128), 256>>>(adj, nullptr);
    // 3) h = tf32(relu(p0 + p1))
    combine_kernel<<<(NTOT * NHID) / (256 * 4), 256>>>();
    // 4) out = h @ h^T  (mma.sync tf32, symmetric dual-write)
    mma_tf32_kernel<1><<<dim3(NTOT / 128, NTOT / 128), 256>>>(nullptr, out);
}

// round 15
// speedup vs baseline: 1.6989x; 1.6989x over previous
#include <cuda_runtime.h>
#include <cstdint>

#define NTOT 8192
#define NHID 256

// ---------------- scratch (allocation-free rule: __device__ globals) --------
__device__ float g_sT[NHID * NTOT];          // support^T, tf32-rounded  [256, 8192]
__device__ float g_h[NTOT * NHID];           // h, tf32-rounded          [8192, 256]
__device__ float g_part[2ll * NTOT * NHID];  // split-K partials of GEMM-2

// ---------------- portable helpers (plain sm_103 target) --------------------
__device__ __forceinline__ float tf32r(float x) {
    uint32_t r;
    asm("cvt.rna.tf32.f32 %0, %1;" : "=r"(r) : "f"(x));
    return __uint_as_float(r);
}
__device__ __forceinline__ uint32_t tf32u(uint32_t x) {
    uint32_t r;
    asm("cvt.rna.tf32.f32 %0, %1;" : "=r"(r) : "f"(__uint_as_float(x)));
    return r;
}
__device__ __forceinline__ uint32_t smem_u32(const void* p) {
    uint32_t a;
    asm("{ .reg .u64 t; cvta.to.shared.u64 t, %1; cvt.u32.u64 %0, t; }"
        : "=r"(a) : "l"(p));
    return a;
}
__device__ __forceinline__ void cp16(uint32_t dst, const void* src) {
    asm volatile("cp.async.cg.shared.global [%0], [%1], 16;"
                 :: "r"(dst), "l"(__cvta_generic_to_global(src)));
}
#define CP_COMMIT() asm volatile("cp.async.commit_group;")
#define CP_WAIT0()  asm volatile("cp.async.wait_group 0;")
#define CP_WAIT1()  asm volatile("cp.async.wait_group 1;")

// mma.sync m16n8k8 tf32 -> f32 (sm_80+ portable)
__device__ __forceinline__ void mma_tf32(float* c, const uint32_t* a, const uint32_t* b) {
    asm volatile(
        "mma.sync.aligned.m16n8k8.row.col.f32.tf32.tf32.f32 "
        "{%0,%1,%2,%3}, {%4,%5,%6,%7}, {%8,%9}, {%0,%1,%2,%3};"
        : "+f"(c[0]), "+f"(c[1]), "+f"(c[2]), "+f"(c[3])
        : "r"(a[0]), "r"(a[1]), "r"(a[2]), "r"(a[3]), "r"(b[0]), "r"(b[1]));
}

// ---------------- smem: 2 stages x (A,B) tiles of 128x16 f32, stride 20 -----
#define TS 20                     // row stride in floats (16 data + 4 pad)
#define TILE_F (128 * TS)         // 2560 floats
#define STAGE_F (2 * TILE_F)      // A + B
// total static: 2 * STAGE_F * 4 = 40960 B  (< 48KB, no opt-in needed)

// ---------------- GEMM-1: fp32 SIMT, epilogue -> support^T (tf32-rounded) ---
__global__ __launch_bounds__(256, 2)
void gemm1_kernel(const float* __restrict__ A, const float* __restrict__ B,
                  const float* __restrict__ bias) {
    __shared__ float As[8][128];
    __shared__ float Bs[8][128];
    const int tid = threadIdx.x;
    const int tx = tid & 15, ty = tid >> 4;
    const int m0 = blockIdx.y * 128, n0 = blockIdx.x * 128;
    float acc[8][8];
#pragma unroll
    for (int i = 0; i < 8; i++)
#pragma unroll
        for (int j = 0; j < 8; j++) acc[i][j] = 0.0f;

    const int a_row = tid >> 1, a_k4 = (tid & 1) * 4;
    const int bn_k = tid >> 5, bn_n4 = (tid & 31) * 4;

    for (int k0 = 0; k0 < NHID; k0 += 8) {
        float4 v = *reinterpret_cast<const float4*>(&A[(long long)(m0 + a_row) * NHID + k0 + a_k4]);
        As[a_k4 + 0][a_row] = v.x; As[a_k4 + 1][a_row] = v.y;
        As[a_k4 + 2][a_row] = v.z; As[a_k4 + 3][a_row] = v.w;
        float4 w = *reinterpret_cast<const float4*>(&B[(long long)(k0 + bn_k) * NHID + n0 + bn_n4]);
        *reinterpret_cast<float4*>(&Bs[bn_k][bn_n4]) = w;
        __syncthreads();
#pragma unroll
        for (int kk = 0; kk < 8; kk++) {
            float a[8], b[8];
            float4 a0 = *reinterpret_cast<const float4*>(&As[kk][ty * 4]);
            float4 a1 = *reinterpret_cast<const float4*>(&As[kk][64 + ty * 4]);
            float4 b0 = *reinterpret_cast<const float4*>(&Bs[kk][tx * 4]);
            float4 b1 = *reinterpret_cast<const float4*>(&Bs[kk][64 + tx * 4]);
            a[0]=a0.x;a[1]=a0.y;a[2]=a0.z;a[3]=a0.w;a[4]=a1.x;a[5]=a1.y;a[6]=a1.z;a[7]=a1.w;
            b[0]=b0.x;b[1]=b0.y;b[2]=b0.z;b[3]=b0.w;b[4]=b1.x;b[5]=b1.y;b[6]=b1.z;b[7]=b1.w;
#pragma unroll
            for (int i = 0; i < 8; i++)
#pragma unroll
                for (int j = 0; j < 8; j++) acc[i][j] = fmaf(a[i], b[j], acc[i][j]);
        }
        __syncthreads();
    }
#pragma unroll
    for (int i = 0; i < 8; i++) {
        const int row = m0 + ((i < 4) ? (ty * 4 + i) : (64 + ty * 4 + (i - 4)));
#pragma unroll
        for (int j = 0; j < 8; j++) {
            const int col = n0 + ((j < 4) ? (tx * 4 + j) : (64 + tx * 4 + (j - 4)));
            g_sT[(size_t)col * NTOT + row] = tf32r(acc[i][j] + bias[col]);
        }
    }
}

// ---------------- mma.sync tf32 kernels --------------------------------------
// MODE 0: GEMM-2 partials. grid (4, 64): nx=x&1, kz=x>>1.  writes g_part.
//         A = adj (raw fp32 via cp.async; fragments tf32-rounded post-LDS).
// MODE 1: GEMM-3 h h^T, symmetric. grid (64, 64); CTAs with x<y exit;
//         block (y,x) computed once, written at (y,x) and (x,y)^T.
template <int MODE>
__global__ __launch_bounds__(256, 2)
void mma_tf32_kernel(const float* __restrict__ A32, float* __restrict__ C) {
    __shared__ float sm[2 * STAGE_F];   // 40960 B static
    const uint32_t sb = smem_u32(sm);

    if (MODE == 1 && blockIdx.x < blockIdx.y) return;  // symmetry: upper triangle only

    const int tid = threadIdx.x;
    const int w = tid >> 5, lane = tid & 31;
    const int g = lane >> 2, t4 = lane & 3;
    const int wm = (w & 3) * 32, wn = (w >> 2) * 64;

    const int m0 = blockIdx.y * 128;
    const int nx = (MODE == 0) ? (blockIdx.x & 1) : blockIdx.x;
    const int kz = (MODE == 0) ? (blockIdx.x >> 1) : 0;
    const int n0 = nx * 128;
    const int kb = (MODE == 0) ? kz * (NTOT / 2) : 0;
    const int T  = (MODE == 0) ? (NTOT / 2) / 16 : NHID / 16;

    float acc[2][8][4];
#pragma unroll
    for (int mi = 0; mi < 2; mi++)
#pragma unroll
        for (int ni = 0; ni < 8; ni++)
#pragma unroll
            for (int q = 0; q < 4; q++) acc[mi][ni][q] = 0.0f;

    // ---- stage loaders (both tiles pure cp.async in both modes) ----
    const float* srcA = (MODE == 0) ? A32 : g_h;
    const long long ldA = (MODE == 0) ? NTOT : NHID;
    const float* srcB = (MODE == 0) ? g_sT : g_h;
    const long long ldB = (MODE == 0) ? NTOT : NHID;

    auto cpA = [&](int k0, int s) {
        const uint32_t base = sb + (uint32_t)(s * STAGE_F) * 4u;
#pragma unroll
        for (int i = 0; i < 2; i++) {
            int j = i * 256 + tid;
            int row = j >> 2, ch = j & 3;
            cp16(base + row * (TS * 4) + ch * 16,
                 srcA + (long long)(m0 + row) * ldA + k0 + ch * 4);
        }
    };
    auto cpB = [&](int k0, int s) {
        const uint32_t base = sb + (uint32_t)(s * STAGE_F + TILE_F) * 4u;
#pragma unroll
        for (int i = 0; i < 2; i++) {
            int j = i * 256 + tid;
            int row = j >> 2, ch = j & 3;
            cp16(base + row * (TS * 4) + ch * 16,
                 srcB + (long long)(n0 + row) * ldB + k0 + ch * 4);
        }
    };

    // ---- prologue: stage 0 ----
    cpA(kb, 0); cpB(kb, 0);
    CP_COMMIT();

    int buf = 0;
    for (int t = 0; t < T; t++) {
        if (t + 1 < T) {
            const int k0 = kb + (t + 1) * 16;
            cpA(k0, buf ^ 1); cpB(k0, buf ^ 1);
            CP_COMMIT();
            CP_WAIT1();
        } else {
            CP_WAIT0();
        }
        __syncthreads();

        const uint32_t* At = reinterpret_cast<const uint32_t*>(sm + buf * STAGE_F);
        const uint32_t* Bt = reinterpret_cast<const uint32_t*>(sm + buf * STAGE_F + TILE_F);
#pragma unroll
        for (int ks = 0; ks < 2; ks++) {
            const int k0 = ks * 8;
            uint32_t Af[2][4];
#pragma unroll
            for (int mi = 0; mi < 2; mi++) {
                const int r = wm + mi * 16 + g;
                Af[mi][0] = At[r * TS + k0 + t4];
                Af[mi][1] = At[(r + 8) * TS + k0 + t4];
                Af[mi][2] = At[r * TS + k0 + t4 + 4];
                Af[mi][3] = At[(r + 8) * TS + k0 + t4 + 4];
                if (MODE == 0) {   // adj arrives raw fp32 -> round fragments
                    Af[mi][0] = tf32u(Af[mi][0]);
                    Af[mi][1] = tf32u(Af[mi][1]);
                    Af[mi][2] = tf32u(Af[mi][2]);
                    Af[mi][3] = tf32u(Af[mi][3]);
                }
            }
            uint32_t Bf[8][2];
#pragma unroll
            for (int ni = 0; ni < 8; ni++) {
                const int rn = wn + ni * 8 + g;
                Bf[ni][0] = Bt[rn * TS + k0 + t4];
                Bf[ni][1] = Bt[rn * TS + k0 + t4 + 4];
            }
#pragma unroll
            for (int mi = 0; mi < 2; mi++)
#pragma unroll
                for (int ni = 0; ni < 8; ni++)
                    mma_tf32(acc[mi][ni], Af[mi], Bf[ni]);
        }
        __syncthreads();
        buf ^= 1;
    }

    // ---- epilogue ----
    if (MODE == 0) {
        float* dst = g_part + (size_t)kz * NTOT * NHID;
#pragma unroll
        for (int mi = 0; mi < 2; mi++)
#pragma unroll
            for (int ni = 0; ni < 8; ni++) {
                const int row = m0 + wm + mi * 16 + g;
                const int col = n0 + wn + ni * 8 + t4 * 2;
                *reinterpret_cast<float2*>(&dst[(size_t)row * NHID + col]) =
                    make_float2(acc[mi][ni][0], acc[mi][ni][1]);
                *reinterpret_cast<float2*>(&dst[(size_t)(row + 8) * NHID + col]) =
                    make_float2(acc[mi][ni][2], acc[mi][ni][3]);
            }
    } else {
        // symmetric dual-write: stage 64-row halves at stride 133
        const bool offdiag = (m0 != n0);
#pragma unroll
        for (int half = 0; half < 2; half++) {
            if (((w & 3) >> 1) == half) {
#pragma unroll
                for (int mi = 0; mi < 2; mi++)
#pragma unroll
                    for (int ni = 0; ni < 8; ni++) {
                        const int lrow = wm - half * 64 + mi * 16 + g;
                        const int col = wn + ni * 8 + t4 * 2;
                        sm[lrow * 133 + col]           = acc[mi][ni][0];
                        sm[lrow * 133 + col + 1]       = acc[mi][ni][1];
                        sm[(lrow + 8) * 133 + col]     = acc[mi][ni][2];
                        sm[(lrow + 8) * 133 + col + 1] = acc[mi][ni][3];
                    }
            }
            __syncthreads();
#pragma unroll
            for (int i = 0; i < 32; i++) {
                const int q = i * 256 + tid;
                const int row = q >> 7, c = q & 127;
                C[(size_t)(m0 + half * 64 + row) * NTOT + n0 + c] = sm[row * 133 + c];
            }
            if (offdiag) {
                const int r = tid & 63, cb = tid >> 6;
#pragma unroll
                for (int c = 0; c < 128; c += 4) {
                    C[(size_t)(n0 + c + cb) * NTOT + m0 + half * 64 + r] =
                        sm[r * 133 + c + cb];
                }
            }
            __syncthreads();
        }
    }
}

// ---------------- combine: h = tf32(relu(p0 + p1)) ---------------------------
__global__ __launch_bounds__(256, 4)
void combine_kernel() {
    const int i4 = (blockIdx.x * 256 + threadIdx.x) * 4;
    float4 a = *reinterpret_cast<const float4*>(&g_part[i4]);
    float4 b = *reinterpret_cast<const float4*>(&g_part[(size_t)NTOT * NHID + i4]);
    float4 o;
    o.x = tf32r(fmaxf(a.x + b.x, 0.0f));
    o.y = tf32r(fmaxf(a.y + b.y, 0.0f));
    o.z = tf32r(fmaxf(a.z + b.z, 0.0f));
    o.w = tf32r(fmaxf(a.w + b.w, 0.0f));
    *reinterpret_cast<float4*>(&g_h[i4]) = o;
}

// ---------------- launch -----------------------------------------------------
extern "C" void kernel_launch(void* const* d_in, const int* in_sizes, int n_in,
                              void* d_out, int out_size) {
    const float* x   = (const float*)d_in[0];
    const float* adj = (const float*)d_in[1];
    const float* W   = (const float*)d_in[2];
    const float* b   = (const float*)d_in[3];
    float* out = (float*)d_out;

    // 1) support^T = tf32(x @ W + b)^T
    gemm1_kernel<<<dim3(NHID / 128, NTOT / 128), 256>>>(x, W, b);
    // 2) split-K partials of adj @ support  (mma.sync tf32, full cp.async)
    mma_tf32_kernel<0><<<dim3(4, NTOT / 128), 256>>>(adj, nullptr);
    // 3) h = tf32(relu(p0 + p1))
    combine_kernel<<<(NTOT * NHID) / (256 * 4), 256>>>();
    // 4) out = h @ h^T  (mma.sync tf32, symmetric dual-write)
    mma_tf32_kernel<1><<<dim3(NTOT / 128, NTOT / 128), 256>>>(nullptr, out);
}